// round 8
// baseline (speedup 1.0000x reference)
#include <cuda_runtime.h>
#include <cuda_bf16.h>

#define N_NODES 100000
#define N_EDGES 3200000
#define IN_CH 128
#define HID 30
#define HPAD 32

// Scratch (allocation-free)
__device__ float g_y[N_NODES * HPAD];    // node features (padded to 32)
__device__ float g_agg[N_NODES * HPAD];  // self + neighbor sums
__device__ int g_idx64;                  // 1 if edge_index is int64, 0 if int32
__device__ int g_cnt[N_NODES];           // in-degree histogram
__device__ int g_offs[N_NODES + 1];      // CSR row offsets (by dst)
__device__ int g_cursor[N_NODES];        // fill cursors
__device__ int g_csr_src[N_EDGES];       // src ids grouped by dst

// ---------------------------------------------------------------------------
// Detect edge_index width (int64 vs int32). Strided samples of high words.
// ---------------------------------------------------------------------------
__global__ void gin_detect_idx(const int* __restrict__ ei32) {
    __shared__ int all_zero;
    if (threadIdx.x == 0) all_zero = 1;
    __syncthreads();
    const int STRIDE = N_EDGES / 2048;
    for (int i = threadIdx.x; i < 2048; i += blockDim.x) {
        int e = i * STRIDE;
        if (ei32[2 * e + 1] != 0) all_zero = 0;
    }
    __syncthreads();
    if (threadIdx.x == 0) g_idx64 = all_zero;
}

// ---------------------------------------------------------------------------
// CSR build: zero counters -> histogram over dst -> scan -> fill src lists
// ---------------------------------------------------------------------------
__global__ void gin_zero_cnt() {
    int i = blockIdx.x * blockDim.x + threadIdx.x;
    if (i < N_NODES) g_cnt[i] = 0;
}

__global__ void gin_hist(const void* __restrict__ ei_raw) {
    int e = blockIdx.x * blockDim.x + threadIdx.x;
    if (e >= N_EDGES) return;
    int d = g_idx64 ? (int)((const long long*)ei_raw)[N_EDGES + e]
                    : ((const int*)ei_raw)[N_EDGES + e];
    atomicAdd(&g_cnt[d], 1);
}

__global__ void gin_scan() {  // single block, 1024 threads
    __shared__ int ssum[1024];
    int tid = threadIdx.x;
    const int CH = (N_NODES + 1023) / 1024;  // 98
    int beg = tid * CH;
    int end = beg + CH; if (end > N_NODES) end = N_NODES;
    int s = 0;
    for (int i = beg; i < end; i++) s += g_cnt[i];
    ssum[tid] = s;
    __syncthreads();
    for (int off = 1; off < 1024; off <<= 1) {
        int v = (tid >= off) ? ssum[tid - off] : 0;
        __syncthreads();
        ssum[tid] += v;
        __syncthreads();
    }
    int run = (tid == 0) ? 0 : ssum[tid - 1];
    for (int i = beg; i < end; i++) {
        g_offs[i] = run;
        g_cursor[i] = run;
        run += g_cnt[i];
    }
    if (tid == 1023) g_offs[N_NODES] = ssum[1023];
}

__global__ void gin_fill(const void* __restrict__ ei_raw) {
    int e = blockIdx.x * blockDim.x + threadIdx.x;
    if (e >= N_EDGES) return;
    int s, d;
    if (g_idx64) {
        const long long* ei = (const long long*)ei_raw;
        s = (int)ei[e];
        d = (int)ei[N_EDGES + e];
    } else {
        const int* ei = (const int*)ei_raw;
        s = ei[e];
        d = ei[N_EDGES + e];
    }
    int pos = atomicAdd(&g_cursor[d], 1);
    g_csr_src[pos] = s;
}

// ---------------------------------------------------------------------------
// Kernel 1: y = x @ w1a (N x 128 -> N x 30, padded). Writes g_y only.
// Weights in shared, padded to stride 32, accessed via LDS.128.
// ---------------------------------------------------------------------------
__global__ void gin_proj1(const float* __restrict__ x, const float* __restrict__ w) {
    __shared__ float ws[64 * 32];  // one 64-row chunk, padded; 8 KB
    float4* ws4 = reinterpret_cast<float4*>(ws);

    int node = blockIdx.x * blockDim.x + threadIdx.x;

    float4 acc[8];
#pragma unroll
    for (int u = 0; u < 8; u++) acc[u] = make_float4(0.f, 0.f, 0.f, 0.f);

    const float4* xr = reinterpret_cast<const float4*>(x + (size_t)node * IN_CH);

    for (int kc = 0; kc < 2; kc++) {
        __syncthreads();
        for (int i = threadIdx.x; i < 64 * 32; i += blockDim.x) {
            int k = i >> 5, c = i & 31;
            ws[i] = (c < HID) ? w[(kc * 64 + k) * HID + c] : 0.f;
        }
        __syncthreads();

        if (node < N_NODES) {
            for (int k4 = 0; k4 < 16; k4++) {
                float4 xv = xr[kc * 16 + k4];
                float xk[4] = {xv.x, xv.y, xv.z, xv.w};
#pragma unroll
                for (int kk = 0; kk < 4; kk++) {
                    int k = k4 * 4 + kk;
                    float t = xk[kk];
#pragma unroll
                    for (int u = 0; u < 8; u++) {
                        float4 wv = ws4[k * 8 + u];
                        acc[u].x += t * wv.x; acc[u].y += t * wv.y;
                        acc[u].z += t * wv.z; acc[u].w += t * wv.w;
                    }
                }
            }
        }
    }

    if (node >= N_NODES) return;
    float4* yo = reinterpret_cast<float4*>(g_y + (size_t)node * HPAD);
#pragma unroll
    for (int u = 0; u < 8; u++) yo[u] = acc[u];
    // zero pad lanes 30,31 (acc[7].z/.w already hold w-padded zeros)
}

// ---------------------------------------------------------------------------
// Kernel 2: CSR gather. 8 threads per node, one float4 each.
// agg[node] = y[node] + sum_{j in in-edges} y[src[j]]
// ---------------------------------------------------------------------------
__global__ void gin_gather() {
    int t = blockIdx.x * blockDim.x + threadIdx.x;
    if (t >= N_NODES * 8) return;
    int node = t >> 3, q = t & 7;

    const float4* yq = reinterpret_cast<const float4*>(g_y);
    float4 acc = yq[node * 8 + q];  // self term

    int j = g_offs[node];
    const int end = g_offs[node + 1];

    for (; j + 1 < end; j += 2) {
        int s0 = __ldg(&g_csr_src[j]);
        int s1 = __ldg(&g_csr_src[j + 1]);
        float4 v0 = __ldg(&yq[s0 * 8 + q]);
        float4 v1 = __ldg(&yq[s1 * 8 + q]);
        acc.x += v0.x + v1.x; acc.y += v0.y + v1.y;
        acc.z += v0.z + v1.z; acc.w += v0.w + v1.w;
    }
    if (j < end) {
        int s0 = __ldg(&g_csr_src[j]);
        float4 v0 = __ldg(&yq[s0 * 8 + q]);
        acc.x += v0.x; acc.y += v0.y; acc.z += v0.z; acc.w += v0.w;
    }

    reinterpret_cast<float4*>(g_agg)[node * 8 + q] = acc;
}

// ---------------------------------------------------------------------------
// Kernel 3: fused node update.
//   t = relu(agg + ba); h = relu(t @ wb + bb); y_next = h @ wa_next
// Weights padded to stride 32 in shared, LDS.128.
// ---------------------------------------------------------------------------
__global__ void gin_fused(const float* __restrict__ ba, const float* __restrict__ wb,
                          const float* __restrict__ bb, const float* __restrict__ wan) {
    __shared__ float swb[HID * 32];
    __shared__ float swan[HID * 32];
    __shared__ float sba[HID];
    __shared__ float sbb4[32];
    float4* swb4 = reinterpret_cast<float4*>(swb);
    float4* swan4 = reinterpret_cast<float4*>(swan);

    for (int i = threadIdx.x; i < HID * 32; i += blockDim.x) {
        int k = i >> 5, c = i & 31;
        float vb = (c < HID) ? wb[k * HID + c] : 0.f;
        float vn = (c < HID) ? wan[k * HID + c] : 0.f;
        swb[i] = vb;
        swan[i] = vn;
    }
    if (threadIdx.x < HID) sba[threadIdx.x] = ba[threadIdx.x];
    if (threadIdx.x < 32) sbb4[threadIdx.x] = (threadIdx.x < HID) ? bb[threadIdx.x] : 0.f;
    __syncthreads();

    int node = blockIdx.x * blockDim.x + threadIdx.x;
    if (node >= N_NODES) return;

    float tt[HID];
    {
        const float4* ar = reinterpret_cast<const float4*>(g_agg + (size_t)node * HPAD);
#pragma unroll
        for (int qq = 0; qq < 8; qq++) {
            float4 v = ar[qq];
            if (qq * 4 + 0 < HID) tt[qq * 4 + 0] = fmaxf(v.x + sba[qq * 4 + 0], 0.f);
            if (qq * 4 + 1 < HID) tt[qq * 4 + 1] = fmaxf(v.y + sba[qq * 4 + 1], 0.f);
            if (qq * 4 + 2 < HID) tt[qq * 4 + 2] = fmaxf(v.z + sba[qq * 4 + 2], 0.f);
            if (qq * 4 + 3 < HID) tt[qq * 4 + 3] = fmaxf(v.w + sba[qq * 4 + 3], 0.f);
        }
    }

    float4 hz[8];
    {
        const float4* bb4 = reinterpret_cast<const float4*>(sbb4);
#pragma unroll
        for (int u = 0; u < 8; u++) hz[u] = bb4[u];
    }
#pragma unroll
    for (int k = 0; k < HID; k++) {
        float t = tt[k];
#pragma unroll
        for (int u = 0; u < 8; u++) {
            float4 wv = swb4[k * 8 + u];
            hz[u].x += t * wv.x; hz[u].y += t * wv.y;
            hz[u].z += t * wv.z; hz[u].w += t * wv.w;
        }
    }
    float hh[HID];
#pragma unroll
    for (int u = 0; u < 8; u++) {
        if (u * 4 + 0 < HID) hh[u * 4 + 0] = fmaxf(hz[u].x, 0.f);
        if (u * 4 + 1 < HID) hh[u * 4 + 1] = fmaxf(hz[u].y, 0.f);
        if (u * 4 + 2 < HID) hh[u * 4 + 2] = fmaxf(hz[u].z, 0.f);
        if (u * 4 + 3 < HID) hh[u * 4 + 3] = fmaxf(hz[u].w, 0.f);
    }

    float4 yz[8];
#pragma unroll
    for (int u = 0; u < 8; u++) yz[u] = make_float4(0.f, 0.f, 0.f, 0.f);
#pragma unroll
    for (int k = 0; k < HID; k++) {
        float t = hh[k];
#pragma unroll
        for (int u = 0; u < 8; u++) {
            float4 wv = swan4[k * 8 + u];
            yz[u].x += t * wv.x; yz[u].y += t * wv.y;
            yz[u].z += t * wv.z; yz[u].w += t * wv.w;
        }
    }

    float4* yo = reinterpret_cast<float4*>(g_y + (size_t)node * HPAD);
#pragma unroll
    for (int u = 0; u < 8; u++) yo[u] = yz[u];  // pad lanes carry zeros via w-padding
}

// ---------------------------------------------------------------------------
// Kernel 4: final layer + log_softmax.
// ---------------------------------------------------------------------------
__global__ void gin_final(const float* __restrict__ ba, const float* __restrict__ wb,
                          const float* __restrict__ bb, float* __restrict__ out) {
    __shared__ float swb[HID * 32];
    __shared__ float sba[HID];
    __shared__ float sbb4[32];
    float4* swb4 = reinterpret_cast<float4*>(swb);

    for (int i = threadIdx.x; i < HID * 32; i += blockDim.x) {
        int k = i >> 5, c = i & 31;
        swb[i] = (c < HID) ? wb[k * HID + c] : 0.f;
    }
    if (threadIdx.x < HID) sba[threadIdx.x] = ba[threadIdx.x];
    if (threadIdx.x < 32) sbb4[threadIdx.x] = (threadIdx.x < HID) ? bb[threadIdx.x] : 0.f;
    __syncthreads();

    int node = blockIdx.x * blockDim.x + threadIdx.x;
    if (node >= N_NODES) return;

    float tt[HID];
    {
        const float4* ar = reinterpret_cast<const float4*>(g_agg + (size_t)node * HPAD);
#pragma unroll
        for (int qq = 0; qq < 8; qq++) {
            float4 v = ar[qq];
            if (qq * 4 + 0 < HID) tt[qq * 4 + 0] = fmaxf(v.x + sba[qq * 4 + 0], 0.f);
            if (qq * 4 + 1 < HID) tt[qq * 4 + 1] = fmaxf(v.y + sba[qq * 4 + 1], 0.f);
            if (qq * 4 + 2 < HID) tt[qq * 4 + 2] = fmaxf(v.z + sba[qq * 4 + 2], 0.f);
            if (qq * 4 + 3 < HID) tt[qq * 4 + 3] = fmaxf(v.w + sba[qq * 4 + 3], 0.f);
        }
    }

    float4 hz[8];
    {
        const float4* bb4 = reinterpret_cast<const float4*>(sbb4);
#pragma unroll
        for (int u = 0; u < 8; u++) hz[u] = bb4[u];
    }
#pragma unroll
    for (int k = 0; k < HID; k++) {
        float t = tt[k];
#pragma unroll
        for (int u = 0; u < 8; u++) {
            float4 wv = swb4[k * 8 + u];
            hz[u].x += t * wv.x; hz[u].y += t * wv.y;
            hz[u].z += t * wv.z; hz[u].w += t * wv.w;
        }
    }

    float hh[32];
#pragma unroll
    for (int u = 0; u < 8; u++) {
        hh[u * 4 + 0] = fmaxf(hz[u].x, 0.f);
        hh[u * 4 + 1] = fmaxf(hz[u].y, 0.f);
        hh[u * 4 + 2] = fmaxf(hz[u].z, 0.f);
        hh[u * 4 + 3] = fmaxf(hz[u].w, 0.f);
    }

    float m = -1e30f;
#pragma unroll
    for (int c = 0; c < HID; c++) m = fmaxf(m, hh[c]);
    float ssum = 0.f;
#pragma unroll
    for (int c = 0; c < HID; c++) ssum += __expf(hh[c] - m);
    float ls = m + logf(ssum);

    float* o = out + (size_t)node * HID;
#pragma unroll
    for (int c = 0; c < HID; c++) o[c] = hh[c] - ls;
}

// ---------------------------------------------------------------------------
extern "C" void kernel_launch(void* const* d_in, const int* in_sizes, int n_in,
                              void* d_out, int out_size) {
    const float* x   = (const float*)d_in[0];
    const void*  ei  = d_in[1];
    const float* w1a = (const float*)d_in[2];
    const float* b1a = (const float*)d_in[3];
    const float* w1b = (const float*)d_in[4];
    const float* b1b = (const float*)d_in[5];
    const float* w2a = (const float*)d_in[6];
    const float* b2a = (const float*)d_in[7];
    const float* w2b = (const float*)d_in[8];
    const float* b2b = (const float*)d_in[9];
    const float* w3a = (const float*)d_in[10];
    const float* b3a = (const float*)d_in[11];
    const float* w3b = (const float*)d_in[12];
    const float* b3b = (const float*)d_in[13];
    float* out = (float*)d_out;

    const int NB_NODE = (N_NODES + 127) / 128;
    const int NB_EDGE = (N_EDGES + 255) / 256;
    const int NB_GATH = (N_NODES * 8 + 255) / 256;

    gin_detect_idx<<<1, 256>>>((const int*)ei);

    // CSR build (once per launch; reused by all 3 layers)
    gin_zero_cnt<<<(N_NODES + 255) / 256, 256>>>();
    gin_hist<<<NB_EDGE, 256>>>(ei);
    gin_scan<<<1, 1024>>>();
    gin_fill<<<NB_EDGE, 256>>>(ei);

    // Layer 1
    gin_proj1<<<NB_NODE, 128>>>(x, w1a);
    gin_gather<<<NB_GATH, 256>>>();
    gin_fused<<<NB_NODE, 128>>>(b1a, w1b, b1b, w2a);
    // Layer 2
    gin_gather<<<NB_GATH, 256>>>();
    gin_fused<<<NB_NODE, 128>>>(b2a, w2b, b2b, w3a);
    // Layer 3
    gin_gather<<<NB_GATH, 256>>>();
    gin_final<<<NB_NODE, 128>>>(b3a, w3b, b3b, out);

    (void)in_sizes; (void)n_in; (void)out_size;
}

// round 9
// speedup vs baseline: 1.5530x; 1.5530x over previous
#include <cuda_runtime.h>
#include <cuda_bf16.h>

#define N_NODES 100000
#define N_EDGES 3200000
#define IN_CH 128
#define HID 30
#define HPAD 32
#define NSB ((N_NODES + 1023) / 1024)   // 98 scan blocks

// Scratch (allocation-free)
__device__ float g_y[N_NODES * HPAD];    // node features (padded to 32)
__device__ float g_agg[N_NODES * HPAD];  // self + neighbor sums
__device__ int g_idx64;                  // 1 if edge_index is int64, 0 if int32
__device__ int g_cnt[N_NODES];           // in-degree histogram
__device__ int g_offs[N_NODES + 1];      // CSR row offsets (by dst)
__device__ int g_cursor[N_NODES];        // fill cursors
__device__ int g_csr_src[N_EDGES];       // src ids grouped by dst
__device__ int g_blocksum[NSB];          // per-scan-block totals
__device__ int g_blockbase[NSB];         // exclusive base per scan block

// ---------------------------------------------------------------------------
// Detect edge_index width (int64 vs int32). Strided samples of high words.
// ---------------------------------------------------------------------------
__global__ void gin_detect_idx(const int* __restrict__ ei32) {
    __shared__ int all_zero;
    if (threadIdx.x == 0) all_zero = 1;
    __syncthreads();
    const int STRIDE = N_EDGES / 2048;
    for (int i = threadIdx.x; i < 2048; i += blockDim.x) {
        int e = i * STRIDE;
        if (ei32[2 * e + 1] != 0) all_zero = 0;
    }
    __syncthreads();
    if (threadIdx.x == 0) g_idx64 = all_zero;
}

// ---------------------------------------------------------------------------
// CSR build: zero -> histogram -> hierarchical scan (3 kernels) -> fill
// ---------------------------------------------------------------------------
__global__ void gin_zero_cnt() {
    int i = blockIdx.x * blockDim.x + threadIdx.x;
    if (i < N_NODES) g_cnt[i] = 0;
}

__global__ void gin_hist(const void* __restrict__ ei_raw) {
    int e = blockIdx.x * blockDim.x + threadIdx.x;
    if (e >= N_EDGES) return;
    int d = g_idx64 ? (int)((const long long*)ei_raw)[N_EDGES + e]
                    : ((const int*)ei_raw)[N_EDGES + e];
    atomicAdd(&g_cnt[d], 1);
}

// Pass 1: per-block inclusive scan of 1024 counts; write EXCLUSIVE values
// into g_offs (without block base) and block total to g_blocksum.
__global__ void gin_scan1() {
    __shared__ int sh[1024];
    int tid = threadIdx.x;
    int gid = blockIdx.x * 1024 + tid;
    int v = (gid < N_NODES) ? g_cnt[gid] : 0;
    sh[tid] = v;
    __syncthreads();
#pragma unroll
    for (int off = 1; off < 1024; off <<= 1) {
        int u = (tid >= off) ? sh[tid - off] : 0;
        __syncthreads();
        sh[tid] += u;
        __syncthreads();
    }
    if (gid < N_NODES) g_offs[gid] = sh[tid] - v;  // exclusive
    if (tid == 1023) g_blocksum[blockIdx.x] = sh[1023];
}

// Pass 2: one block scans the NSB block totals (exclusive).
__global__ void gin_scan2() {
    __shared__ int sh[128];
    int tid = threadIdx.x;  // blockDim = 128 >= NSB
    int v = (tid < NSB) ? g_blocksum[tid] : 0;
    sh[tid] = v;
    __syncthreads();
#pragma unroll
    for (int off = 1; off < 128; off <<= 1) {
        int u = (tid >= off) ? sh[tid - off] : 0;
        __syncthreads();
        sh[tid] += u;
        __syncthreads();
    }
    if (tid < NSB) g_blockbase[tid] = sh[tid] - v;  // exclusive base
    if (tid == 0) g_offs[N_NODES] = N_EDGES;
}

// Pass 3: add block base; initialize cursors.
__global__ void gin_scan3() {
    int gid = blockIdx.x * 1024 + threadIdx.x;
    if (gid >= N_NODES) return;
    int o = g_offs[gid] + g_blockbase[blockIdx.x];
    g_offs[gid] = o;
    g_cursor[gid] = o;
}

__global__ void gin_fill(const void* __restrict__ ei_raw) {
    int e = blockIdx.x * blockDim.x + threadIdx.x;
    if (e >= N_EDGES) return;
    int s, d;
    if (g_idx64) {
        const long long* ei = (const long long*)ei_raw;
        s = (int)ei[e];
        d = (int)ei[N_EDGES + e];
    } else {
        const int* ei = (const int*)ei_raw;
        s = ei[e];
        d = ei[N_EDGES + e];
    }
    int pos = atomicAdd(&g_cursor[d], 1);
    g_csr_src[pos] = s;
}

// ---------------------------------------------------------------------------
// Kernel 1: y = x @ w1a (N x 128 -> N x 30, padded). Writes g_y only.
// ---------------------------------------------------------------------------
__global__ void gin_proj1(const float* __restrict__ x, const float* __restrict__ w) {
    __shared__ float ws[64 * 32];  // one 64-row chunk, padded; 8 KB
    float4* ws4 = reinterpret_cast<float4*>(ws);

    int node = blockIdx.x * blockDim.x + threadIdx.x;

    float4 acc[8];
#pragma unroll
    for (int u = 0; u < 8; u++) acc[u] = make_float4(0.f, 0.f, 0.f, 0.f);

    const float4* xr = reinterpret_cast<const float4*>(x + (size_t)node * IN_CH);

    for (int kc = 0; kc < 2; kc++) {
        __syncthreads();
        for (int i = threadIdx.x; i < 64 * 32; i += blockDim.x) {
            int k = i >> 5, c = i & 31;
            ws[i] = (c < HID) ? w[(kc * 64 + k) * HID + c] : 0.f;
        }
        __syncthreads();

        if (node < N_NODES) {
            for (int k4 = 0; k4 < 16; k4++) {
                float4 xv = xr[kc * 16 + k4];
                float xk[4] = {xv.x, xv.y, xv.z, xv.w};
#pragma unroll
                for (int kk = 0; kk < 4; kk++) {
                    int k = k4 * 4 + kk;
                    float t = xk[kk];
#pragma unroll
                    for (int u = 0; u < 8; u++) {
                        float4 wv = ws4[k * 8 + u];
                        acc[u].x += t * wv.x; acc[u].y += t * wv.y;
                        acc[u].z += t * wv.z; acc[u].w += t * wv.w;
                    }
                }
            }
        }
    }

    if (node >= N_NODES) return;
    float4* yo = reinterpret_cast<float4*>(g_y + (size_t)node * HPAD);
#pragma unroll
    for (int u = 0; u < 8; u++) yo[u] = acc[u];
}

// ---------------------------------------------------------------------------
// Kernel 2: CSR gather. 8 threads per node, one float4 each.
// ---------------------------------------------------------------------------
__global__ void gin_gather() {
    int t = blockIdx.x * blockDim.x + threadIdx.x;
    if (t >= N_NODES * 8) return;
    int node = t >> 3, q = t & 7;

    const float4* yq = reinterpret_cast<const float4*>(g_y);
    float4 acc = yq[node * 8 + q];  // self term

    int j = g_offs[node];
    const int end = g_offs[node + 1];

    for (; j + 1 < end; j += 2) {
        int s0 = __ldg(&g_csr_src[j]);
        int s1 = __ldg(&g_csr_src[j + 1]);
        float4 v0 = __ldg(&yq[s0 * 8 + q]);
        float4 v1 = __ldg(&yq[s1 * 8 + q]);
        acc.x += v0.x + v1.x; acc.y += v0.y + v1.y;
        acc.z += v0.z + v1.z; acc.w += v0.w + v1.w;
    }
    if (j < end) {
        int s0 = __ldg(&g_csr_src[j]);
        float4 v0 = __ldg(&yq[s0 * 8 + q]);
        acc.x += v0.x; acc.y += v0.y; acc.z += v0.z; acc.w += v0.w;
    }

    reinterpret_cast<float4*>(g_agg)[node * 8 + q] = acc;
}

// ---------------------------------------------------------------------------
// Kernel 3: fused node update.
// ---------------------------------------------------------------------------
__global__ void gin_fused(const float* __restrict__ ba, const float* __restrict__ wb,
                          const float* __restrict__ bb, const float* __restrict__ wan) {
    __shared__ float swb[HID * 32];
    __shared__ float swan[HID * 32];
    __shared__ float sba[HID];
    __shared__ float sbb4[32];
    float4* swb4 = reinterpret_cast<float4*>(swb);
    float4* swan4 = reinterpret_cast<float4*>(swan);

    for (int i = threadIdx.x; i < HID * 32; i += blockDim.x) {
        int k = i >> 5, c = i & 31;
        swb[i] = (c < HID) ? wb[k * HID + c] : 0.f;
        swan[i] = (c < HID) ? wan[k * HID + c] : 0.f;
    }
    if (threadIdx.x < HID) sba[threadIdx.x] = ba[threadIdx.x];
    if (threadIdx.x < 32) sbb4[threadIdx.x] = (threadIdx.x < HID) ? bb[threadIdx.x] : 0.f;
    __syncthreads();

    int node = blockIdx.x * blockDim.x + threadIdx.x;
    if (node >= N_NODES) return;

    float tt[HID];
    {
        const float4* ar = reinterpret_cast<const float4*>(g_agg + (size_t)node * HPAD);
#pragma unroll
        for (int qq = 0; qq < 8; qq++) {
            float4 v = ar[qq];
            if (qq * 4 + 0 < HID) tt[qq * 4 + 0] = fmaxf(v.x + sba[qq * 4 + 0], 0.f);
            if (qq * 4 + 1 < HID) tt[qq * 4 + 1] = fmaxf(v.y + sba[qq * 4 + 1], 0.f);
            if (qq * 4 + 2 < HID) tt[qq * 4 + 2] = fmaxf(v.z + sba[qq * 4 + 2], 0.f);
            if (qq * 4 + 3 < HID) tt[qq * 4 + 3] = fmaxf(v.w + sba[qq * 4 + 3], 0.f);
        }
    }

    float4 hz[8];
    {
        const float4* bb4 = reinterpret_cast<const float4*>(sbb4);
#pragma unroll
        for (int u = 0; u < 8; u++) hz[u] = bb4[u];
    }
#pragma unroll
    for (int k = 0; k < HID; k++) {
        float t = tt[k];
#pragma unroll
        for (int u = 0; u < 8; u++) {
            float4 wv = swb4[k * 8 + u];
            hz[u].x += t * wv.x; hz[u].y += t * wv.y;
            hz[u].z += t * wv.z; hz[u].w += t * wv.w;
        }
    }
    float hh[HID];
#pragma unroll
    for (int u = 0; u < 8; u++) {
        if (u * 4 + 0 < HID) hh[u * 4 + 0] = fmaxf(hz[u].x, 0.f);
        if (u * 4 + 1 < HID) hh[u * 4 + 1] = fmaxf(hz[u].y, 0.f);
        if (u * 4 + 2 < HID) hh[u * 4 + 2] = fmaxf(hz[u].z, 0.f);
        if (u * 4 + 3 < HID) hh[u * 4 + 3] = fmaxf(hz[u].w, 0.f);
    }

    float4 yz[8];
#pragma unroll
    for (int u = 0; u < 8; u++) yz[u] = make_float4(0.f, 0.f, 0.f, 0.f);
#pragma unroll
    for (int k = 0; k < HID; k++) {
        float t = hh[k];
#pragma unroll
        for (int u = 0; u < 8; u++) {
            float4 wv = swan4[k * 8 + u];
            yz[u].x += t * wv.x; yz[u].y += t * wv.y;
            yz[u].z += t * wv.z; yz[u].w += t * wv.w;
        }
    }

    float4* yo = reinterpret_cast<float4*>(g_y + (size_t)node * HPAD);
#pragma unroll
    for (int u = 0; u < 8; u++) yo[u] = yz[u];
}

// ---------------------------------------------------------------------------
// Kernel 4: final layer + log_softmax.
// ---------------------------------------------------------------------------
__global__ void gin_final(const float* __restrict__ ba, const float* __restrict__ wb,
                          const float* __restrict__ bb, float* __restrict__ out) {
    __shared__ float swb[HID * 32];
    __shared__ float sba[HID];
    __shared__ float sbb4[32];
    float4* swb4 = reinterpret_cast<float4*>(swb);

    for (int i = threadIdx.x; i < HID * 32; i += blockDim.x) {
        int k = i >> 5, c = i & 31;
        swb[i] = (c < HID) ? wb[k * HID + c] : 0.f;
    }
    if (threadIdx.x < HID) sba[threadIdx.x] = ba[threadIdx.x];
    if (threadIdx.x < 32) sbb4[threadIdx.x] = (threadIdx.x < HID) ? bb[threadIdx.x] : 0.f;
    __syncthreads();

    int node = blockIdx.x * blockDim.x + threadIdx.x;
    if (node >= N_NODES) return;

    float tt[HID];
    {
        const float4* ar = reinterpret_cast<const float4*>(g_agg + (size_t)node * HPAD);
#pragma unroll
        for (int qq = 0; qq < 8; qq++) {
            float4 v = ar[qq];
            if (qq * 4 + 0 < HID) tt[qq * 4 + 0] = fmaxf(v.x + sba[qq * 4 + 0], 0.f);
            if (qq * 4 + 1 < HID) tt[qq * 4 + 1] = fmaxf(v.y + sba[qq * 4 + 1], 0.f);
            if (qq * 4 + 2 < HID) tt[qq * 4 + 2] = fmaxf(v.z + sba[qq * 4 + 2], 0.f);
            if (qq * 4 + 3 < HID) tt[qq * 4 + 3] = fmaxf(v.w + sba[qq * 4 + 3], 0.f);
        }
    }

    float4 hz[8];
    {
        const float4* bb4 = reinterpret_cast<const float4*>(sbb4);
#pragma unroll
        for (int u = 0; u < 8; u++) hz[u] = bb4[u];
    }
#pragma unroll
    for (int k = 0; k < HID; k++) {
        float t = tt[k];
#pragma unroll
        for (int u = 0; u < 8; u++) {
            float4 wv = swb4[k * 8 + u];
            hz[u].x += t * wv.x; hz[u].y += t * wv.y;
            hz[u].z += t * wv.z; hz[u].w += t * wv.w;
        }
    }

    float hh[32];
#pragma unroll
    for (int u = 0; u < 8; u++) {
        hh[u * 4 + 0] = fmaxf(hz[u].x, 0.f);
        hh[u * 4 + 1] = fmaxf(hz[u].y, 0.f);
        hh[u * 4 + 2] = fmaxf(hz[u].z, 0.f);
        hh[u * 4 + 3] = fmaxf(hz[u].w, 0.f);
    }

    float m = -1e30f;
#pragma unroll
    for (int c = 0; c < HID; c++) m = fmaxf(m, hh[c]);
    float ssum = 0.f;
#pragma unroll
    for (int c = 0; c < HID; c++) ssum += __expf(hh[c] - m);
    float ls = m + logf(ssum);

    float* o = out + (size_t)node * HID;
#pragma unroll
    for (int c = 0; c < HID; c++) o[c] = hh[c] - ls;
}

// ---------------------------------------------------------------------------
extern "C" void kernel_launch(void* const* d_in, const int* in_sizes, int n_in,
                              void* d_out, int out_size) {
    const float* x   = (const float*)d_in[0];
    const void*  ei  = d_in[1];
    const float* w1a = (const float*)d_in[2];
    const float* b1a = (const float*)d_in[3];
    const float* w1b = (const float*)d_in[4];
    const float* b1b = (const float*)d_in[5];
    const float* w2a = (const float*)d_in[6];
    const float* b2a = (const float*)d_in[7];
    const float* w2b = (const float*)d_in[8];
    const float* b2b = (const float*)d_in[9];
    const float* w3a = (const float*)d_in[10];
    const float* b3a = (const float*)d_in[11];
    const float* w3b = (const float*)d_in[12];
    const float* b3b = (const float*)d_in[13];
    float* out = (float*)d_out;

    const int NB_NODE = (N_NODES + 127) / 128;
    const int NB_EDGE = (N_EDGES + 255) / 256;
    const int NB_GATH = (N_NODES * 8 + 255) / 256;

    gin_detect_idx<<<1, 256>>>((const int*)ei);

    // CSR build (once per launch; reused by all 3 layers)
    gin_zero_cnt<<<(N_NODES + 255) / 256, 256>>>();
    gin_hist<<<NB_EDGE, 256>>>(ei);
    gin_scan1<<<NSB, 1024>>>();
    gin_scan2<<<1, 128>>>();
    gin_scan3<<<NSB, 1024>>>();
    gin_fill<<<NB_EDGE, 256>>>(ei);

    // Layer 1
    gin_proj1<<<NB_NODE, 128>>>(x, w1a);
    gin_gather<<<NB_GATH, 256>>>();
    gin_fused<<<NB_NODE, 128>>>(b1a, w1b, b1b, w2a);
    // Layer 2
    gin_gather<<<NB_GATH, 256>>>();
    gin_fused<<<NB_NODE, 128>>>(b2a, w2b, b2b, w3a);
    // Layer 3
    gin_gather<<<NB_GATH, 256>>>();
    gin_final<<<NB_NODE, 128>>>(b3a, w3b, b3b, out);

    (void)in_sizes; (void)n_in; (void)out_size;
}